// round 9
// baseline (speedup 1.0000x reference)
#include <cuda_runtime.h>
#include <cuda_bf16.h>
#include <cstdint>

// Problem constants
#define BB   32      // batch
#define DD   4096    // model dim
#define HH   32      // q heads
#define HKV  8       // kv heads
#define GG   4       // q heads per kv head
#define DH   128     // head dim
#define TT   4096    // cache length
#define EQKV 6144    // 4096 + 1024 + 1024
#define SPLITS 16    // K-splits for projections
#define DSPL 256     // d per split (4096/16)
#define XSTR 36      // padded smem stride (floats) for x tile: 144B, 16B-aligned

// attention split config
#define TCH    512   // tokens per CTA
#define NSPLIT 8     // TT / TCH

// ---------------- scratch (device globals; no runtime allocation) ----------------
__device__ float g_v [BB * HKV * DH];
__device__ float g_q [BB * HH * DH];
__device__ float g_k [BB * HKV * DH];
__device__ float g_attn[BB * HH * DH];
__device__ float g_P1[SPLITS * BB * EQKV];               // qkv partials
__device__ float g_P2[SPLITS * BB * DD];                 // wo partials
__device__ float g_pacc[BB * HKV * NSPLIT * GG * DH];    // flash partial acc
__device__ float g_pml [BB * HKV * NSPLIT * GG * 2];     // flash partial (m,l)

// ---------------- packed fp32x2 helpers (FFMA2 path, sm_100+) ----------------
__device__ __forceinline__ unsigned long long pk2(float lo, float hi) {
    unsigned long long r;
    asm("mov.b64 %0, {%1,%2};" : "=l"(r) : "f"(lo), "f"(hi));
    return r;
}
__device__ __forceinline__ void upk2(unsigned long long v, float& lo, float& hi) {
    asm("mov.b64 {%0,%1}, %2;" : "=f"(lo), "=f"(hi) : "l"(v));
}
__device__ __forceinline__ void fma2(unsigned long long& d, unsigned long long a, unsigned long long b) {
    asm("fma.rn.f32x2 %0, %1, %2, %0;" : "+l"(d) : "l"(a), "l"(b));
}

// ---------------- projection GEMV body ----------------
// out[b][e] = sum_d x[b][d] * w[d][e].  256 threads.
// Thread = (col-pair c2, batch-half bh): 2 adjacent cols, 16 batches (8 fp32x2 pairs).
// Weight rows double-buffered 8-deep: loads for block i+1 in flight while block i computes.
__device__ __forceinline__ void proj_row8(
    unsigned long long acc[8][2], const float2* wr,
    const float* __restrict__ xs, int dbase, int bh)
{
    #pragma unroll
    for (int u = 0; u < 8; u++) {
        unsigned long long wA = pk2(wr[u].x, wr[u].x);
        unsigned long long wB = pk2(wr[u].y, wr[u].y);
        const float* xrow = xs + (dbase + u) * XSTR + bh * 16;
        #pragma unroll
        for (int jq = 0; jq < 4; jq++) {
            ulonglong2 xv = *(const ulonglong2*)(xrow + jq * 4);  // 4 batches (bcast)
            fma2(acc[2 * jq + 0][0], wA, xv.x);
            fma2(acc[2 * jq + 0][1], wB, xv.x);
            fma2(acc[2 * jq + 1][0], wA, xv.y);
            fma2(acc[2 * jq + 1][1], wB, xv.y);
        }
    }
}

__device__ __forceinline__ void proj_body(
    const float* __restrict__ x, const float* __restrict__ w,
    int Ew, int le0, int gcol0, int d0,
    float* __restrict__ part, int partE)
{
    __shared__ float xs[DSPL * XSTR];   // 36 KB, [d_local][b], rows 16B-aligned
    const int tid = threadIdx.x;

    // coalesced gather: thread reads float4 rows of x, transposes into smem
    {
        int bb = tid >> 3, lo = tid & 7;
        #pragma unroll
        for (int it = 0; it < DSPL / 32; it++) {
            int d = lo * 4 + it * 32;
            float4 xv = *(const float4*)(x + (size_t)bb * DD + d0 + d);
            xs[(d + 0) * XSTR + bb] = xv.x;
            xs[(d + 1) * XSTR + bb] = xv.y;
            xs[(d + 2) * XSTR + bb] = xv.z;
            xs[(d + 3) * XSTR + bb] = xv.w;
        }
    }
    __syncthreads();

    const int c2 = tid & 127;     // col pair index (cols c2*2, c2*2+1)
    const int bh = tid >> 7;      // batch half

    unsigned long long acc[8][2];
    #pragma unroll
    for (int p = 0; p < 8; p++) { acc[p][0] = 0ull; acc[p][1] = 0ull; }

    const float* wp = w + (size_t)d0 * Ew + le0 + c2 * 2;

    float2 wA[8], wB[8];
    #pragma unroll
    for (int u = 0; u < 8; u++) wA[u] = *(const float2*)(wp + (size_t)u * Ew);
    wp += (size_t)8 * Ew;

    const int NBLK = DSPL / 8;   // 32 (even)
    for (int base = 0; base < NBLK; base += 2) {
        // load rows for block base+1 (always exists: NBLK even)
        #pragma unroll
        for (int u = 0; u < 8; u++) wB[u] = *(const float2*)(wp + (size_t)u * Ew);
        wp += (size_t)8 * Ew;
        proj_row8(acc, wA, xs, base * 8, bh);
        // load rows for block base+2 (unless done)
        if (base + 2 < NBLK) {
            #pragma unroll
            for (int u = 0; u < 8; u++) wA[u] = *(const float2*)(wp + (size_t)u * Ew);
            wp += (size_t)8 * Ew;
        }
        proj_row8(acc, wB, xs, (base + 1) * 8, bh);
    }

    const int split = blockIdx.y;
    float* pb = part + (size_t)split * BB * partE + gcol0 + c2 * 2;
    #pragma unroll
    for (int p = 0; p < 8; p++) {
        float loA, hiA, loB, hiB;
        upk2(acc[p][0], loA, hiA);
        upk2(acc[p][1], loB, hiB);
        int b0 = bh * 16 + 2 * p;
        *(float2*)(pb + (size_t)b0 * partE)       = make_float2(loA, loB);
        *(float2*)(pb + (size_t)(b0 + 1) * partE) = make_float2(hiA, hiB);
    }
}

__global__ void __launch_bounds__(256)
proj_qkv_kernel(const float* __restrict__ x, const float* __restrict__ wq,
                const float* __restrict__ wk, const float* __restrict__ wv)
{
    int e0 = blockIdx.x * 256;
    const float* w; int Ew, le0;
    if (e0 < 4096)      { w = wq; Ew = 4096; le0 = e0; }
    else if (e0 < 5120) { w = wk; Ew = 1024; le0 = e0 - 4096; }
    else                { w = wv; Ew = 1024; le0 = e0 - 5120; }
    proj_body(x, w, Ew, le0, e0, blockIdx.y * DSPL, g_P1, EQKV);
}

__global__ void __launch_bounds__(256)
proj_o_kernel(const float* __restrict__ wo)
{
    int e0 = blockIdx.x * 256;
    proj_body(g_attn, wo, DD, e0, e0, blockIdx.y * DSPL, g_P2, DD);
}

// ---------------- fused split-reduce + RoPE ----------------
// grid (48, BB), block 128.  hh<32: q head; 32..39: k head; 40..47: v head (no rotate).
__global__ void __launch_bounds__(128)
fused_reduce_rot_kernel(const float* __restrict__ rot, int rot_b_stride)
{
    const int hh = blockIdx.x, b = blockIdx.y, tid = threadIdx.x;
    int col;
    if (hh < 32)      col = hh * 128 + tid;
    else if (hh < 40) col = 4096 + (hh - 32) * 128 + tid;
    else              col = 5120 + (hh - 40) * 128 + tid;

    const float* p = g_P1 + (size_t)b * EQKV + col;
    float s = 0.f;
    #pragma unroll
    for (int sp = 0; sp < SPLITS; sp++)
        s += p[(size_t)sp * BB * EQKV];

    if (hh >= 40) {                      // v: plain reduce
        g_v[(size_t)b * 1024 + (hh - 40) * 128 + tid] = s;
        return;
    }

    __shared__ float xsr[DH];
    xsr[tid] = s;
    __syncthreads();
    const float* R = rot + (size_t)b * rot_b_stride;
    float a = 0.f;
    #pragma unroll 8
    for (int dd = 0; dd < DH; dd++) a += xsr[dd] * R[dd * DH + tid];

    if (hh < 32) g_q[(size_t)(b * HH + hh) * DH + tid] = a;
    else         g_k[(size_t)(b * HKV + (hh - 32)) * DH + tid] = a;
}

// ---------------- reduce wo partials ----------------
__global__ void reduce_o_kernel(float* __restrict__ out)
{
    int idx = blockIdx.x * 256 + threadIdx.x;
    if (idx >= BB * DD) return;
    int b = idx >> 12, col = idx & 4095;
    float s = 0.f;
    #pragma unroll
    for (int sp = 0; sp < SPLITS; sp++)
        s += g_P2[((size_t)sp * BB + b) * DD + col];
    out[b * DD + col] = s;
}

// ---------------- flash decode: direct-LDG, 512 tokens/CTA, single-pass softmax ----------------
// grid (NSPLIT, HKV, BB), block 256 (8 warps x 64 tokens).
__global__ void __launch_bounds__(256, 3)
attn_kernel(const float* __restrict__ kc, const float* __restrict__ vc,
            const int* __restrict__ sp_ptr)
{
    __shared__ float s_q  [GG * DH];       // scaled q, [g][d]
    __shared__ float s_sc [TCH * GG];      // scores -> probs, [token][g] (float4)
    __shared__ float s_wm [8 * GG];        // per-warp max
    __shared__ float s_sl [8 * GG];        // per-warp exp-sums
    __shared__ float s_MM [GG];            // block max
    __shared__ float s_out[8 * GG * DH];   // per-warp value partials

    const int chunk = blockIdx.x, kvh = blockIdx.y, b = blockIdx.z;
    const int sp = *sp_ptr;
    const int t0 = chunk * TCH;
    if (t0 > sp) return;

    const int tid = threadIdx.x;
    const int wid = tid >> 5, lane = tid & 31;
    const int bkv = b * HKV + kvh;

    const float* kbase = kc + (size_t)bkv * TT * DH;
    const float* vbase = vc + (size_t)bkv * TT * DH;
    const float* gk = g_k + (size_t)bkv * DH;
    const float* gv = g_v + (size_t)bkv * DH;

    // stage scaled q
    if (tid < 128) {
        int g = tid >> 5, c = tid & 31;
        const float sc = 0.08838834764831845f;   // 1/sqrt(128)
        float4 qv = *(const float4*)(g_q + (size_t)(b * HH + kvh * GG + g) * DH + c * 4);
        ((float4*)s_q)[g * 32 + c] = make_float4(qv.x * sc, qv.y * sc, qv.z * sc, qv.w * sc);
    }
    __syncthreads();

    // ---------------- score phase ----------------
    const int tokg = lane >> 4, dg = lane & 15;
    const int jb = wid * 64;

    float4 qr0[GG], qr1[GG];
    #pragma unroll
    for (int g = 0; g < GG; g++) {
        qr0[g] = *(const float4*)(s_q + g * DH + dg * 4);
        qr1[g] = *(const float4*)(s_q + g * DH + dg * 4 + 64);
    }

    float wm0 = -1e30f, wm1 = -1e30f, wm2 = -1e30f, wm3 = -1e30f;
    float4 ka, kb;
    {
        int t = t0 + jb + tokg;
        const float* kp = (t == sp) ? gk : (kbase + (size_t)t * DH);
        ka = *(const float4*)(kp + dg * 4);
        kb = *(const float4*)(kp + dg * 4 + 64);
    }
    #pragma unroll 8
    for (int it = 0; it < 32; it++) {
        int jl = jb + it * 2 + tokg;
        int t = t0 + jl;
        float4 ca = ka, cb = kb;
        if (it < 31) {
            int tn = t0 + jb + (it + 1) * 2 + tokg;
            const float* kp = (tn == sp) ? gk : (kbase + (size_t)tn * DH);
            ka = *(const float4*)(kp + dg * 4);
            kb = *(const float4*)(kp + dg * 4 + 64);
        }
        float s0 = ca.x*qr0[0].x + ca.y*qr0[0].y + ca.z*qr0[0].z + ca.w*qr0[0].w
                 + cb.x*qr1[0].x + cb.y*qr1[0].y + cb.z*qr1[0].z + cb.w*qr1[0].w;
        float s1 = ca.x*qr0[1].x + ca.y*qr0[1].y + ca.z*qr0[1].z + ca.w*qr0[1].w
                 + cb.x*qr1[1].x + cb.y*qr1[1].y + cb.z*qr1[1].z + cb.w*qr1[1].w;
        float s2 = ca.x*qr0[2].x + ca.y*qr0[2].y + ca.z*qr0[2].z + ca.w*qr0[2].w
                 + cb.x*qr1[2].x + cb.y*qr1[2].y + cb.z*qr1[2].z + cb.w*qr1[2].w;
        float s3 = ca.x*qr0[3].x + ca.y*qr0[3].y + ca.z*qr0[3].z + ca.w*qr0[3].w
                 + cb.x*qr1[3].x + cb.y*qr1[3].y + cb.z*qr1[3].z + cb.w*qr1[3].w;
        #pragma unroll
        for (int off = 1; off <= 8; off <<= 1) {
            s0 += __shfl_xor_sync(0xffffffffu, s0, off);
            s1 += __shfl_xor_sync(0xffffffffu, s1, off);
            s2 += __shfl_xor_sync(0xffffffffu, s2, off);
            s3 += __shfl_xor_sync(0xffffffffu, s3, off);
        }
        if (t > sp) { s0 = s1 = s2 = s3 = -1e30f; }
        if (dg == 0)
            ((float4*)s_sc)[jl] = make_float4(s0, s1, s2, s3);
        wm0 = fmaxf(wm0, s0); wm1 = fmaxf(wm1, s1);
        wm2 = fmaxf(wm2, s2); wm3 = fmaxf(wm3, s3);
    }
    wm0 = fmaxf(wm0, __shfl_xor_sync(0xffffffffu, wm0, 16));
    wm1 = fmaxf(wm1, __shfl_xor_sync(0xffffffffu, wm1, 16));
    wm2 = fmaxf(wm2, __shfl_xor_sync(0xffffffffu, wm2, 16));
    wm3 = fmaxf(wm3, __shfl_xor_sync(0xffffffffu, wm3, 16));
    if (lane == 0) {
        s_wm[wid * 4 + 0] = wm0; s_wm[wid * 4 + 1] = wm1;
        s_wm[wid * 4 + 2] = wm2; s_wm[wid * 4 + 3] = wm3;
    }
    __syncthreads();

    if (tid < 4) {
        float m = s_wm[tid];
        #pragma unroll
        for (int w = 1; w < 8; w++) m = fmaxf(m, s_wm[w * 4 + tid]);
        s_MM[tid] = m;
    }
    __syncthreads();

    // exp + per-warp sums (thread = 2 tokens)
    {
        float4 sva = ((float4*)s_sc)[tid];
        float4 svb = ((float4*)s_sc)[tid + 256];
        float m0 = s_MM[0], m1 = s_MM[1], m2 = s_MM[2], m3 = s_MM[3];
        float pa0 = __expf(sva.x - m0), pb0 = __expf(svb.x - m0);
        float pa1 = __expf(sva.y - m1), pb1 = __expf(svb.y - m1);
        float pa2 = __expf(sva.z - m2), pb2 = __expf(svb.z - m2);
        float pa3 = __expf(sva.w - m3), pb3 = __expf(svb.w - m3);
        ((float4*)s_sc)[tid]       = make_float4(pa0, pa1, pa2, pa3);
        ((float4*)s_sc)[tid + 256] = make_float4(pb0, pb1, pb2, pb3);
        float p0 = pa0 + pb0, p1 = pa1 + pb1, p2 = pa2 + pb2, p3 = pa3 + pb3;
        #pragma unroll
        for (int off = 1; off <= 16; off <<= 1) {
            p0 += __shfl_xor_sync(0xffffffffu, p0, off);
            p1 += __shfl_xor_sync(0xffffffffu, p1, off);
            p2 += __shfl_xor_sync(0xffffffffu, p2, off);
            p3 += __shfl_xor_sync(0xffffffffu, p3, off);
        }
        if (lane == 0) {
            s_sl[wid * 4 + 0] = p0; s_sl[wid * 4 + 1] = p1;
            s_sl[wid * 4 + 2] = p2; s_sl[wid * 4 + 3] = p3;
        }
    }
    __syncthreads();

    if (tid < 4) {
        float L = 0.f;
        #pragma unroll
        for (int w = 0; w < 8; w++) L += s_sl[w * 4 + tid];
        size_t mlb = (((size_t)bkv * NSPLIT + chunk) * GG + tid) * 2;
        g_pml[mlb] = s_MM[tid];
        g_pml[mlb + 1] = L;
    }

    // ---------------- value phase ----------------
    float4 a0 = {0,0,0,0}, a1 = {0,0,0,0}, a2 = {0,0,0,0}, a3 = {0,0,0,0};
    #pragma unroll 4
    for (int jo = 0; jo < 64; jo += 4) {
        float4 vv[4], p4[4];
        #pragma unroll
        for (int u = 0; u < 4; u++) {
            int t = t0 + jb + jo + u;
            const float* vp = (t == sp) ? gv : (vbase + (size_t)t * DH);
            vv[u] = *(const float4*)(vp + lane * 4);
            p4[u] = ((float4*)s_sc)[jb + jo + u];
        }
        #pragma unroll
        for (int u = 0; u < 4; u++) {
            a0.x += p4[u].x*vv[u].x; a0.y += p4[u].x*vv[u].y; a0.z += p4[u].x*vv[u].z; a0.w += p4[u].x*vv[u].w;
            a1.x += p4[u].y*vv[u].x; a1.y += p4[u].y*vv[u].y; a1.z += p4[u].y*vv[u].z; a1.w += p4[u].y*vv[u].w;
            a2.x += p4[u].z*vv[u].x; a2.y += p4[u].z*vv[u].y; a2.z += p4[u].z*vv[u].z; a2.w += p4[u].z*vv[u].w;
            a3.x += p4[u].w*vv[u].x; a3.y += p4[u].w*vv[u].y; a3.z += p4[u].w*vv[u].z; a3.w += p4[u].w*vv[u].w;
        }
    }
    {
        float* ob = s_out + wid * (GG * DH);
        *(float4*)(ob + 0 * DH + lane * 4) = a0;
        *(float4*)(ob + 1 * DH + lane * 4) = a1;
        *(float4*)(ob + 2 * DH + lane * 4) = a2;
        *(float4*)(ob + 3 * DH + lane * 4) = a3;
    }
    __syncthreads();

    size_t obase = (((size_t)bkv * NSPLIT + chunk) * GG) * DH;
    #pragma unroll
    for (int r = tid; r < GG * DH; r += 256) {
        float s = 0.f;
        #pragma unroll
        for (int w = 0; w < 8; w++) s += s_out[w * (GG * DH) + r];
        g_pacc[obase + r] = s;
    }
}

// ---------------- combine split-KV partials ----------------
__global__ void combine_kernel(const int* __restrict__ sp_ptr)
{
    const int h = blockIdx.x, b = blockIdx.y, d = threadIdx.x;
    const int sp = *sp_ptr;
    const int nact = sp / TCH + 1;
    const int kvh = h >> 2, g = h & 3;
    const int bkv = b * HKV + kvh;

    float M = -1e30f;
    for (int c = 0; c < nact; c++)
        M = fmaxf(M, g_pml[(((size_t)bkv * NSPLIT + c) * GG + g) * 2]);

    float L = 0.f, acc = 0.f;
    for (int c = 0; c < nact; c++) {
        size_t mlb = (((size_t)bkv * NSPLIT + c) * GG + g) * 2;
        float f = __expf(g_pml[mlb] - M);
        L += g_pml[mlb + 1] * f;
        acc += g_pacc[(((size_t)bkv * NSPLIT + c) * GG + g) * DH + d] * f;
    }
    g_attn[(size_t)(b * HH + h) * DH + d] = acc / L;
}

// ---------------- launcher ----------------
extern "C" void kernel_launch(void* const* d_in, const int* in_sizes, int n_in,
                              void* d_out, int out_size)
{
    const float* x   = (const float*)d_in[0];
    const float* wq  = (const float*)d_in[1];
    const float* wk  = (const float*)d_in[2];
    const float* wv  = (const float*)d_in[3];
    const float* wo  = (const float*)d_in[4];
    const float* rot = (const float*)d_in[5];
    // d_in[6] = attn_mask: not read (semantics derived from start_pos)
    const float* kc  = (const float*)d_in[7];
    const float* vc  = (const float*)d_in[8];
    const int*   sp  = (const int*)d_in[9];
    float* out = (float*)d_out;

    int rot_b_stride = (in_sizes[5] >= BB * DH * DH) ? DH * DH : 0;

    proj_qkv_kernel<<<dim3(EQKV / 256, SPLITS), 256>>>(x, wq, wk, wv);
    fused_reduce_rot_kernel<<<dim3(48, BB), 128>>>(rot, rot_b_stride);
    attn_kernel<<<dim3(NSPLIT, HKV, BB), 256>>>(kc, vc, sp);
    combine_kernel<<<dim3(HH, BB), DH>>>(sp);
    proj_o_kernel<<<dim3(DD / 256, SPLITS), 256>>>(wo);
    reduce_o_kernel<<<(BB * DD + 255) / 256, 256>>>(out);
}